// round 17
// baseline (speedup 1.0000x reference)
#include <cuda_runtime.h>
#include <cuda_fp16.h>
#include <cstdint>

#define NUM_TOKENS 8192
#define HIDDEN 4096
#define NUM_EXPERTS 8
#define INTER 2048
#define GU_COLS 4096
#define MAX_TILES 72
#define NSTAGE 3

// block schedule: chunk0 = 1824 prep; chunks 1..7 = 2112 (288 g1 + 1824 prep);
// then 288 g1 (last group); then 2304 g2.  total 19200
#define CHUNK0 1824
#define CHUNKN 2112
#define G1_TAIL_START 16608     /* 1824 + 7*2112 */
#define G2_START 16896          /* + 288 */
#define MEGA_BLOCKS 19200
#define PW2_TOTAL 4096

// ---------------- scratch ----------------
__device__ int g_counts[NUM_EXPERTS];
__device__ int g_lists[NUM_EXPERTS][NUM_TOKENS];
__device__ int g_is64;
__device__ int g_t1done[MAX_TILES];
__device__ int g_pxdone[MAX_TILES];
__device__ int g_w1done[NUM_EXPERTS * 32];
__device__ int g_pwdone;
// fp16 A-fragment packed activations: [tile][kf16][mf 8][lane 32][4 b32]
__device__ uint32_t g_xpackh[(size_t)MAX_TILES * (HIDDEN / 16) * 8 * 32 * 4];
__device__ uint32_t g_interph[(size_t)MAX_TILES * (INTER / 16) * 8 * 32 * 4];
// fp16 B-fragment packed weights
__device__ uint32_t g_wp1[(size_t)NUM_EXPERTS * 32 * 256 * 2 * 8 * 32 * 2];
__device__ uint32_t g_wp2[(size_t)NUM_EXPERTS * 32 * 128 * 16 * 32 * 2];

// ---------------- helpers ----------------
__device__ __forceinline__ uint32_t smem_u32(const void* p) {
    uint32_t a;
    asm("{ .reg .u64 t; cvta.to.shared.u64 t, %1; cvt.u32.u64 %0, t; }" : "=r"(a) : "l"(p));
    return a;
}
__device__ __forceinline__ uint32_t f2h2(float lo, float hi) {
    __half2 h = __floats2half2_rn(lo, hi);
    return *(uint32_t*)&h;
}
__device__ __forceinline__ void mma16(float* d, const uint32_t* a, uint32_t b0, uint32_t b1) {
    asm volatile(
        "mma.sync.aligned.m16n8k16.row.col.f32.f16.f16.f32 "
        "{%0,%1,%2,%3},{%4,%5,%6,%7},{%8,%9},{%0,%1,%2,%3};"
        : "+f"(d[0]), "+f"(d[1]), "+f"(d[2]), "+f"(d[3])
        : "r"(a[0]), "r"(a[1]), "r"(a[2]), "r"(a[3]), "r"(b0), "r"(b1));
}
__device__ __forceinline__ void cpa16(uint32_t dst, const void* src) {
    asm volatile("cp.async.cg.shared.global [%0], [%1], 16;" :: "r"(dst), "l"(src));
}
__device__ __forceinline__ void cpa_commit() { asm volatile("cp.async.commit_group;" ::: "memory"); }
__device__ __forceinline__ void cpa_wait1()  { asm volatile("cp.async.wait_group 1;" ::: "memory"); }
__device__ __forceinline__ void cpa_wait0()  { asm volatile("cp.async.wait_group 0;" ::: "memory"); }

__device__ __forceinline__ float silu(float g) { return g / (1.0f + __expf(-g)); }

__device__ __forceinline__ int find_tile(int t, int* e_out, int* m0_out, int* cnt_out) {
    int acc = 0;
#pragma unroll
    for (int e = 0; e < NUM_EXPERTS; e++) {
        int c = g_counts[e];
        int nt = (c + 127) >> 7;
        if (t < acc + nt) { *e_out = e; *m0_out = (t - acc) << 7; *cnt_out = c; return 1; }
        acc += nt;
    }
    return 0;
}

// ---------------- routing ----------------
__global__ void detect_kernel(const int* __restrict__ t32) {
    if (threadIdx.x == 0) {
        int all_zero = 1;
        for (int i = 0; i < 256; i++) {
            int idx = 2 * (i * (NUM_TOKENS / 256)) + 1;
            if (t32[idx] != 0) { all_zero = 0; break; }
        }
        g_is64 = all_zero;
        g_pwdone = 0;
    }
    if (threadIdx.x < NUM_EXPERTS) g_counts[threadIdx.x] = 0;
    if (threadIdx.x < MAX_TILES) { g_t1done[threadIdx.x] = 0; g_pxdone[threadIdx.x] = 0; }
    if (threadIdx.x < NUM_EXPERTS * 32) g_w1done[threadIdx.x] = 0;
}

__global__ void route_kernel(const int* __restrict__ t32) {
    int i = blockIdx.x * blockDim.x + threadIdx.x;
    if (i < NUM_TOKENS) {
        int v = g_is64 ? t32[2 * i] : t32[i];
        int e = v & 7;
        int p = atomicAdd(&g_counts[e], 1);
        g_lists[e][p] = i;
    }
}

// ---------------- prep bodies (MLP-boosted: all loads batched before cvt/store) ----------------
__device__ void pw1_body(const float* __restrict__ gup, int kb, int nt, int e) {
    const int tid = threadIdx.x;
    const int w = tid >> 5, lane = tid & 31;
    const int g = lane >> 2, tq = lane & 3;
    const int kf = kb * 8 + w;             // 0..255
    const float* W = gup + (size_t)e * HIDDEN * GU_COLS;
    const int k0 = kf * 16 + tq * 2;
    float a0[16], a1[16], a2[16], a3[16];
#pragma unroll
    for (int i = 0; i < 16; i++) {
        int gu = i >> 3, nf = i & 7;
        const float* Wc = W + gu * INTER + nt * 64 + nf * 8 + g;
        a0[i] = Wc[(size_t)k0 * GU_COLS];
        a1[i] = Wc[(size_t)(k0 + 1) * GU_COLS];
        a2[i] = Wc[(size_t)(k0 + 8) * GU_COLS];
        a3[i] = Wc[(size_t)(k0 + 9) * GU_COLS];
    }
#pragma unroll
    for (int i = 0; i < 16; i++) {
        int gu = i >> 3, nf = i & 7;
        uint2 o;
        o.x = f2h2(a0[i], a1[i]);
        o.y = f2h2(a2[i], a3[i]);
        size_t off = ((((((size_t)e * 32 + nt) * 256 + kf) * 2 + gu) * 8 + nf) * 32 + lane) * 2;
        *(uint2*)(g_wp1 + off) = o;
    }
    __threadfence();
    __syncthreads();
    if (tid == 0) atomicAdd(&g_w1done[e * 32 + nt], 1);
}

__device__ void px_body(const float* __restrict__ x, int* tokS, int kb, int tile) {
    int e, m0, count;
    if (!find_tile(tile, &e, &m0, &count)) return;
    const int tid = threadIdx.x;
    const int w = tid >> 5, lane = tid & 31;
    const int g = lane >> 2, tq = lane & 3;
    if (tid < 128) tokS[tid] = (m0 + tid < count) ? g_lists[e][m0 + tid] : -1;
    __syncthreads();
    const int kf = kb * 8 + w;
    const int c0 = kf * 16 + 2 * tq;
    const float2 zero = make_float2(0.f, 0.f);
    float2 v00[8], v01[8], v10[8], v11[8];
#pragma unroll
    for (int mf = 0; mf < 8; mf++) {
        int r0 = mf * 16 + g;
        int t0 = tokS[r0], t1 = tokS[r0 + 8];
        v00[mf] = zero; v01[mf] = zero; v10[mf] = zero; v11[mf] = zero;
        if (t0 >= 0) {
            const float* p0 = x + (size_t)t0 * HIDDEN + c0;
            v00[mf] = *(const float2*)p0;
            v01[mf] = *(const float2*)(p0 + 8);
        }
        if (t1 >= 0) {
            const float* p1 = x + (size_t)t1 * HIDDEN + c0;
            v10[mf] = *(const float2*)p1;
            v11[mf] = *(const float2*)(p1 + 8);
        }
    }
#pragma unroll
    for (int mf = 0; mf < 8; mf++) {
        uint4 o;
        o.x = f2h2(v00[mf].x, v00[mf].y);
        o.y = f2h2(v10[mf].x, v10[mf].y);
        o.z = f2h2(v01[mf].x, v01[mf].y);
        o.w = f2h2(v11[mf].x, v11[mf].y);
        size_t off = ((((size_t)tile * (HIDDEN / 16) + kf) * 8 + mf) * 32 + lane) * 4;
        *(uint4*)(g_xpackh + off) = o;
    }
    __threadfence();
    __syncthreads();
    if (tid == 0) atomicAdd(&g_pxdone[tile], 1);
}

__device__ void pw2_body(const float* __restrict__ down, int idx) {
    const int bx = idx & 15, nt = (idx >> 4) & 31, e = idx >> 9;
    const int tid = threadIdx.x;
    const int w = tid >> 5, lane = tid & 31;
    const int g = lane >> 2, tq = lane & 3;
    const int kf = bx * 8 + w;             // 0..127
    const float* W = down + (size_t)e * INTER * HIDDEN;
    const int k0 = kf * 16 + tq * 2;
    float a0[16], a1[16], a2[16], a3[16];
#pragma unroll
    for (int nf = 0; nf < 16; nf++) {
        const float* Wc = W + nt * 128 + nf * 8 + g;
        a0[nf] = Wc[(size_t)k0 * HIDDEN];
        a1[nf] = Wc[(size_t)(k0 + 1) * HIDDEN];
        a2[nf] = Wc[(size_t)(k0 + 8) * HIDDEN];
        a3[nf] = Wc[(size_t)(k0 + 9) * HIDDEN];
    }
#pragma unroll
    for (int nf = 0; nf < 16; nf++) {
        uint2 o;
        o.x = f2h2(a0[nf], a1[nf]);
        o.y = f2h2(a2[nf], a3[nf]);
        size_t off = (((((size_t)e * 32 + nt) * 128 + kf) * 16 + nf) * 32 + lane) * 2;
        *(uint2*)(g_wp2 + off) = o;
    }
    __threadfence();
    __syncthreads();
    if (tid == 0) atomicAdd(&g_pwdone, 1);
}

// smem: per stage [A 16KB][B 16KB], BK=64 (4 kf16)
#define STAGE_BYTES 32768
#define GEMM_SMEM (NSTAGE * STAGE_BYTES)   /* 98304 */

// ---------------- gemm bodies ----------------
__device__ void gemm1_body(char* smem, int nt, int t_id) {
    int e, m0, count;
    if (!find_tile(t_id, &e, &m0, &count)) return;

    const uint32_t sb = smem_u32(smem);
    const int tid = threadIdx.x;
    const int wid = tid >> 5, lane = tid & 31;
    const int mw = wid >> 2, nw = wid & 3;
    const int g = lane >> 2, tq = lane & 3;

    // wait for inputs: this tile's pack_x and this (e,nt)'s pack_w1
    if (tid == 0) {
        while (atomicAdd(&g_pxdone[t_id], 0) < 32) {}
        while (atomicAdd(&g_w1done[e * 32 + nt], 0) < 32) {}
        __threadfence();
    }
    __syncthreads();

    const uint32_t* xA = g_xpackh + (size_t)t_id * (HIDDEN / 16) * 1024;
    const uint32_t* wB = g_wp1 + (((size_t)e * 32 + nt) * 256) * 1024;

    auto issue = [&](int kc, int soff) {
        const uint32_t* As = xA + (size_t)kc * 4096;
        const uint32_t* Bs = wB + (size_t)kc * 4096;
#pragma unroll
        for (int j = 0; j < 4; j++) {
            int idx = tid + j * 256;
            cpa16(sb + soff + idx * 16, As + idx * 4);
            cpa16(sb + soff + 16384 + idx * 16, Bs + idx * 4);
        }
    };

    float accg[4][2][4] = {};
    float accu[4][2][4] = {};

    issue(0, 0);
    cpa_commit();
    issue(1, STAGE_BYTES);
    cpa_commit();

    const int NK = HIDDEN / 64;
    int soff_c = 0, soff_p = 2 * STAGE_BYTES;
    for (int kc = 0; kc < NK; kc++) {
        if (kc + 1 < NK) cpa_wait1(); else cpa_wait0();
        __syncthreads();
        if (kc + 2 < NK) {
            issue(kc + 2, soff_p);
            cpa_commit();
        }

#pragma unroll
        for (int kk = 0; kk < 4; kk++) {
            uint2 bg[2], bu[2];
#pragma unroll
            for (int ni = 0; ni < 2; ni++) {
                bg[ni] = *(const uint2*)(smem + soff_c + 16384 +
                            ((kk * 2 + 0) * 8 + nw * 2 + ni) * 256 + lane * 8);
                bu[ni] = *(const uint2*)(smem + soff_c + 16384 +
                            ((kk * 2 + 1) * 8 + nw * 2 + ni) * 256 + lane * 8);
            }
#pragma unroll
            for (int mi = 0; mi < 4; mi++) {
                const uint4 a = *(const uint4*)(smem + soff_c +
                            ((kk * 8 + mw * 4 + mi) * 32 + lane) * 16);
                mma16(accg[mi][0], &a.x, bg[0].x, bg[0].y);
                mma16(accg[mi][1], &a.x, bg[1].x, bg[1].y);
                mma16(accu[mi][0], &a.x, bu[0].x, bu[0].y);
                mma16(accu[mi][1], &a.x, bu[1].x, bu[1].y);
            }
        }
        soff_c += STAGE_BYTES; if (soff_c == NSTAGE * STAGE_BYTES) soff_c = 0;
        soff_p += STAGE_BYTES; if (soff_p == NSTAGE * STAGE_BYTES) soff_p = 0;
    }

    const int kf = nt * 4 + nw;
#pragma unroll
    for (int mi = 0; mi < 4; mi++) {
        int mf = mw * 4 + mi;
        uint4 o;
        {
            float v0 = silu(accg[mi][0][0]) * accu[mi][0][0];
            float v1 = silu(accg[mi][0][1]) * accu[mi][0][1];
            float v2 = silu(accg[mi][0][2]) * accu[mi][0][2];
            float v3 = silu(accg[mi][0][3]) * accu[mi][0][3];
            o.x = f2h2(v0, v1);
            o.y = f2h2(v2, v3);
        }
        {
            float v0 = silu(accg[mi][1][0]) * accu[mi][1][0];
            float v1 = silu(accg[mi][1][1]) * accu[mi][1][1];
            float v2 = silu(accg[mi][1][2]) * accu[mi][1][2];
            float v3 = silu(accg[mi][1][3]) * accu[mi][1][3];
            o.z = f2h2(v0, v1);
            o.w = f2h2(v2, v3);
        }
        size_t off = ((((size_t)t_id * (INTER / 16) + kf) * 8 + mf) * 32 + (g * 4 + tq)) * 4;
        *(uint4*)(g_interph + off) = o;
    }

    __threadfence();
    __syncthreads();
    if (tid == 0) atomicAdd(&g_t1done[t_id], 1);
}

__device__ void gemm2_body(char* smem, int* tokS, float* __restrict__ out, int nt, int t_id) {
    int e, m0, count;
    if (!find_tile(t_id, &e, &m0, &count)) return;
    const int n0 = nt * 128;

    const uint32_t sb = smem_u32(smem);
    const int tid = threadIdx.x;
    const int wid = tid >> 5, lane = tid & 31;
    const int mw = wid >> 2, nw = wid & 3;
    const int g = lane >> 2, tq = lane & 3;

    if (tid == 0) {
        while (atomicAdd(&g_pwdone, 0) < PW2_TOTAL) {}
        while (atomicAdd(&g_t1done[t_id], 0) < 32) {}
        __threadfence();
    }
    __syncthreads();
    if (tid < 128) tokS[tid] = (m0 + tid < count) ? g_lists[e][m0 + tid] : -1;
    __syncthreads();

    const uint32_t* xA = g_interph + (size_t)t_id * (INTER / 16) * 1024;
    const uint32_t* wB = g_wp2 + (((size_t)e * 32 + nt) * 128) * 1024;

    auto issue = [&](int kc, int soff) {
        const uint32_t* As = xA + (size_t)kc * 4096;
        const uint32_t* Bs = wB + (size_t)kc * 4096;
#pragma unroll
        for (int j = 0; j < 4; j++) {
            int idx = tid + j * 256;
            cpa16(sb + soff + idx * 16, As + idx * 4);
            cpa16(sb + soff + 16384 + idx * 16, Bs + idx * 4);
        }
    };

    float acc[4][4][4] = {};

    issue(0, 0);
    cpa_commit();
    issue(1, STAGE_BYTES);
    cpa_commit();

    const int NK = INTER / 64;
    int soff_c = 0, soff_p = 2 * STAGE_BYTES;
    for (int kc = 0; kc < NK; kc++) {
        if (kc + 1 < NK) cpa_wait1(); else cpa_wait0();
        __syncthreads();
        if (kc + 2 < NK) {
            issue(kc + 2, soff_p);
            cpa_commit();
        }

#pragma unroll
        for (int kk = 0; kk < 4; kk++) {
            uint2 bb[4];
#pragma unroll
            for (int ni = 0; ni < 4; ni++)
                bb[ni] = *(const uint2*)(smem + soff_c + 16384 +
                            (kk * 16 + nw * 4 + ni) * 256 + lane * 8);
#pragma unroll
            for (int mi = 0; mi < 4; mi++) {
                const uint4 a = *(const uint4*)(smem + soff_c +
                            ((kk * 8 + mw * 4 + mi) * 32 + lane) * 16);
#pragma unroll
                for (int ni = 0; ni < 4; ni++)
                    mma16(acc[mi][ni], &a.x, bb[ni].x, bb[ni].y);
            }
        }
        soff_c += STAGE_BYTES; if (soff_c == NSTAGE * STAGE_BYTES) soff_c = 0;
        soff_p += STAGE_BYTES; if (soff_p == NSTAGE * STAGE_BYTES) soff_p = 0;
    }

#pragma unroll
    for (int mi = 0; mi < 4; mi++) {
        int r0 = mw * 64 + mi * 16 + g;
        int t0 = tokS[r0], t1 = tokS[r0 + 8];
#pragma unroll
        for (int ni = 0; ni < 4; ni++) {
            int col = n0 + nw * 32 + ni * 8 + 2 * tq;
            if (t0 >= 0)
                *(float2*)(out + (size_t)t0 * HIDDEN + col) =
                    make_float2(acc[mi][ni][0], acc[mi][ni][1]);
            if (t1 >= 0)
                *(float2*)(out + (size_t)t1 * HIDDEN + col) =
                    make_float2(acc[mi][ni][2], acc[mi][ni][3]);
        }
    }
}

// ---------------- mega kernel: ordered chunks (prep || gemm1) then gemm2 ----------------
// prep index j (0..1823) + expert chunk c -> body
__device__ __forceinline__ void run_prep(const float* gup, const float* x, const float* down,
                                         int* tokS, int j, int c) {
    if (j < 1024) {
        pw1_body(gup, j & 31, (j >> 5) & 31, c);
    } else if (j < 1312) {
        int q = j - 1024;
        px_body(x, tokS, q & 31, 9 * c + (q >> 5));
    } else {
        pw2_body(down, c * 512 + (j - 1312));
    }
}

__global__ __launch_bounds__(256, 2) void mega_kernel(const float* __restrict__ gup,
                                                      const float* __restrict__ x,
                                                      const float* __restrict__ down,
                                                      float* __restrict__ out) {
    extern __shared__ char smem[];
    __shared__ int tokS[128];
    const int fid = blockIdx.x;

    if (fid < CHUNK0) {
        run_prep(gup, x, down, tokS, fid, 0);
    } else if (fid < G1_TAIL_START) {
        const int t = fid - CHUNK0;
        const int c = 1 + t / CHUNKN;
        const int i = t % CHUNKN;
        if (i < 2016) {
            const int gi = i / 7, p = i % 7;
            if (p == 0) {
                const int idx = (c - 1) * 288 + gi;      // g1 for previous chunk's tiles
                gemm1_body(smem, idx & 31, idx >> 5);
            } else {
                run_prep(gup, x, down, tokS, gi * 6 + (p - 1), c);
            }
        } else {
            run_prep(gup, x, down, tokS, 1728 + (i - 2016), c);
        }
    } else if (fid < G2_START) {
        const int idx = 7 * 288 + (fid - G1_TAIL_START); // last g1 group (tiles 63..71)
        gemm1_body(smem, idx & 31, idx >> 5);
    } else {
        const int idx = fid - G2_START;
        gemm2_body(smem, tokS, out, idx & 31, idx >> 5);
    }
}

// ---------------- launch ----------------
extern "C" void kernel_launch(void* const* d_in, const int* in_sizes, int n_in,
                              void* d_out, int out_size) {
    const float* x    = (const float*)d_in[0];
    const int*   tids = (const int*)d_in[1];
    const float* gup  = (const float*)d_in[2];
    const float* down = (const float*)d_in[3];
    float*       out  = (float*)d_out;

    cudaFuncSetAttribute(mega_kernel, cudaFuncAttributeMaxDynamicSharedMemorySize, GEMM_SMEM);

    detect_kernel<<<1, 256>>>(tids);
    route_kernel<<<NUM_TOKENS / 256, 256>>>(tids);
    mega_kernel<<<MEGA_BLOCKS, 256, GEMM_SMEM>>>(gup, x, down, out);
}